// round 2
// baseline (speedup 1.0000x reference)
#include <cuda_runtime.h>

#define BATCH 16
#define CDIM 256
#define HWDIM 2304
#define PB (CDIM * HWDIM)            // 589824 floats per batch

// Scratch (device globals — allocation-free per harness rules)
__device__ float g_inv[BATCH];
__device__ float g_S[(size_t)BATCH * HWDIM * HWDIM];   // 339.7 MB: relu(G*inv)^2
__device__ float g_T[(size_t)BATCH * PB];              // 37.7 MB : 1x1-conv result

// ---------------------------------------------------------------------------
// Kernel 1: per-batch inverse squared L2 norm
// ---------------------------------------------------------------------------
__global__ void sumsq_kernel(const float* __restrict__ x) {
    const int b = blockIdx.x;
    const float4* p = (const float4*)(x + (size_t)b * PB);
    const int n4 = PB / 4;  // 147456
    float s = 0.f;
    for (int i = threadIdx.x; i < n4; i += blockDim.x) {
        float4 v = p[i];
        s += v.x * v.x + v.y * v.y + v.z * v.z + v.w * v.w;
    }
    __shared__ float red[512];
    red[threadIdx.x] = s;
    __syncthreads();
    for (int off = blockDim.x >> 1; off > 0; off >>= 1) {
        if (threadIdx.x < (unsigned)off) red[threadIdx.x] += red[threadIdx.x + off];
        __syncthreads();
    }
    if (threadIdx.x == 0) g_inv[b] = 1.0f / red[0];
}

// ---------------------------------------------------------------------------
// Generic 128x128x8 SGEMM, 256 threads, 8x8 microtiles (strided 4+4 fragments)
//   C[M,N] = A(row-major, lda) @ B(row-major, ldb)   all dims multiples of tile
// EPI 0: C = relu(acc * g_inv[bz])^2            (GEMM1 -> g_S)
// EPI 1: C = acc + bias[row]                    (GEMM2 -> g_T)
// EPI 2: C = acc                                (GEMM3 -> d_out; A=g_S, B=g_T)
// ---------------------------------------------------------------------------
template <int EPI>
__global__ void __launch_bounds__(256, 2)
sgemm128(const float* __restrict__ Ag, int lda, size_t sA,
         const float* __restrict__ Bg, int ldb, size_t sB,
         float* __restrict__ Cg, int ldc, size_t sC,
         int K, const float* __restrict__ bias)
{
    const int bz = blockIdx.z;
    const float* A;
    const float* Bp;
    float* Cp;
    if (EPI == 2) {        // GEMM3: Y = S @ Tview
        A  = g_S + (size_t)bz * sA;
        Bp = g_T + (size_t)bz * sB;
        Cp = Cg  + (size_t)bz * sC;
    } else if (EPI == 0) { // GEMM1: G = M1 @ M2 (both views of x)
        A  = Ag + (size_t)bz * sA;
        Bp = Bg + (size_t)bz * sB;
        Cp = g_S + (size_t)bz * sC;
    } else {               // GEMM2: T = W @ X
        A  = Ag;                       // W, shared across batches
        Bp = Bg + (size_t)bz * sB;
        Cp = g_T + (size_t)bz * sC;
    }

    const int m0 = blockIdx.y * 128;
    const int n0 = blockIdx.x * 128;

    __shared__ float As[8][132];   // padded to reduce transpose-store conflicts
    __shared__ float Bs[8][128];

    const int tid = threadIdx.x;
    const int tx = tid & 15;       // 0..15  -> col groups {tx*4, 64+tx*4}
    const int ty = tid >> 4;       // 0..15  -> row groups {ty*4, 64+ty*4}

    float acc[8][8];
#pragma unroll
    for (int i = 0; i < 8; i++)
#pragma unroll
        for (int j = 0; j < 8; j++) acc[i][j] = 0.f;

    // global-load assignments
    const int arow = tid >> 1;         // 0..127
    const int akq  = (tid & 1) * 4;    // 0 or 4
    const int bk   = tid >> 5;         // 0..7
    const int bn   = (tid & 31) * 4;   // 0..124

    const float* aptr = A  + (size_t)(m0 + arow) * lda + akq;
    const float* bptr = Bp + (size_t)bk * ldb + n0 + bn;

    // prefetch first tiles
    float4 av = *(const float4*)(aptr);
    float4 bv = *(const float4*)(bptr);

    for (int k0 = 0; k0 < K; k0 += 8) {
        __syncthreads();   // previous iteration's reads are done
        As[akq + 0][arow] = av.x;
        As[akq + 1][arow] = av.y;
        As[akq + 2][arow] = av.z;
        As[akq + 3][arow] = av.w;
        *(float4*)&Bs[bk][bn] = bv;
        __syncthreads();

        // prefetch next tiles (overlaps with compute below)
        if (k0 + 8 < K) {
            av = *(const float4*)(aptr + (k0 + 8));
            bv = *(const float4*)(bptr + (size_t)(k0 + 8) * ldb);
        }

#pragma unroll
        for (int k = 0; k < 8; k++) {
            float a[8], b[8];
            *(float4*)&a[0] = *(const float4*)&As[k][ty * 4];
            *(float4*)&a[4] = *(const float4*)&As[k][64 + ty * 4];
            *(float4*)&b[0] = *(const float4*)&Bs[k][tx * 4];
            *(float4*)&b[4] = *(const float4*)&Bs[k][64 + tx * 4];
#pragma unroll
            for (int i = 0; i < 8; i++)
#pragma unroll
                for (int j = 0; j < 8; j++) acc[i][j] = fmaf(a[i], b[j], acc[i][j]);
        }
    }

    // epilogue
    float inv = 0.f;
    if (EPI == 0) inv = g_inv[bz];

#pragma unroll
    for (int ri = 0; ri < 2; ri++) {
#pragma unroll
        for (int i = 0; i < 4; i++) {
            const int gr = m0 + ri * 64 + ty * 4 + i;
            float brow = 0.f;
            if (EPI == 1) brow = bias[gr];
#pragma unroll
            for (int ci = 0; ci < 2; ci++) {
                float4 v;
                v.x = acc[ri * 4 + i][ci * 4 + 0];
                v.y = acc[ri * 4 + i][ci * 4 + 1];
                v.z = acc[ri * 4 + i][ci * 4 + 2];
                v.w = acc[ri * 4 + i][ci * 4 + 3];
                if (EPI == 0) {
                    float r;
                    r = fmaxf(v.x * inv, 0.f); v.x = r * r;
                    r = fmaxf(v.y * inv, 0.f); v.y = r * r;
                    r = fmaxf(v.z * inv, 0.f); v.z = r * r;
                    r = fmaxf(v.w * inv, 0.f); v.w = r * r;
                } else if (EPI == 1) {
                    v.x += brow; v.y += brow; v.z += brow; v.w += brow;
                }
                *(float4*)&Cp[(size_t)gr * ldc + n0 + ci * 64 + tx * 4] = v;
            }
        }
    }
}

// ---------------------------------------------------------------------------
// Launch
//   d_in[0] = x    (16,256,48,48) f32
//   d_in[1] = W    (256,256)      f32
//   d_in[2] = bias (256,)         f32
//   d_out   = y    (16,256,48,48) f32
// ---------------------------------------------------------------------------
extern "C" void kernel_launch(void* const* d_in, const int* in_sizes, int n_in,
                              void* d_out, int out_size)
{
    const float* x    = (const float*)d_in[0];
    const float* W    = (const float*)d_in[1];
    const float* bias = (const float*)d_in[2];
    float* out        = (float*)d_out;

    // 1) per-batch 1/||x||^2
    sumsq_kernel<<<BATCH, 512>>>(x);

    // 2) GEMM2: T[o,p] = W @ X + bias   (independent of step 1)
    {
        dim3 grid(HWDIM / 128, CDIM / 128, BATCH);
        sgemm128<1><<<grid, 256>>>(W, CDIM, 0,
                                   x, HWDIM, (size_t)PB,
                                   nullptr, HWDIM, (size_t)PB,
                                   CDIM, bias);
    }

    // 3) GEMM1: S[n,m] = relu( (M1 @ M2) * inv )^2
    {
        dim3 grid(HWDIM / 128, HWDIM / 128, BATCH);
        sgemm128<0><<<grid, 256>>>(x, CDIM, (size_t)PB,
                                   x, HWDIM, (size_t)PB,
                                   nullptr, HWDIM, (size_t)HWDIM * HWDIM,
                                   CDIM, nullptr);
    }

    // 4) GEMM3: Y[n,j] = S @ Tview  -> d_out directly
    {
        dim3 grid(CDIM / 128, HWDIM / 128, BATCH);
        sgemm128<2><<<grid, 256>>>(nullptr, HWDIM, (size_t)HWDIM * HWDIM,
                                   nullptr, CDIM, (size_t)PB,
                                   out, CDIM, (size_t)PB,
                                   HWDIM, nullptr);
    }
}

// round 3
// speedup vs baseline: 1.0004x; 1.0004x over previous
#include <cuda_runtime.h>

#define BATCH 16
#define CDIM 256
#define HWDIM 2304
#define PB (CDIM * HWDIM)            // 589824 floats per batch

// Scratch (device globals — allocation-free per harness rules)
__device__ float g_inv[BATCH];
__device__ float g_S[(size_t)BATCH * HWDIM * HWDIM];   // 339.7 MB: relu(G*inv)^2
__device__ float g_T[(size_t)BATCH * PB];              // 37.7 MB : 1x1-conv result

// ---------------------------------------------------------------------------
// Kernel 1: per-batch inverse squared L2 norm
// ---------------------------------------------------------------------------
__global__ void sumsq_kernel(const float* __restrict__ x) {
    const int b = blockIdx.x;
    const float4* p = (const float4*)(x + (size_t)b * PB);
    const int n4 = PB / 4;  // 147456
    float s = 0.f;
    for (int i = threadIdx.x; i < n4; i += blockDim.x) {
        float4 v = p[i];
        s += v.x * v.x + v.y * v.y + v.z * v.z + v.w * v.w;
    }
    __shared__ float red[512];
    red[threadIdx.x] = s;
    __syncthreads();
    for (int off = blockDim.x >> 1; off > 0; off >>= 1) {
        if (threadIdx.x < (unsigned)off) red[threadIdx.x] += red[threadIdx.x + off];
        __syncthreads();
    }
    if (threadIdx.x == 0) g_inv[b] = 1.0f / red[0];
}

// ---------------------------------------------------------------------------
// Generic 128x128x8 SGEMM, 256 threads, 8x8 microtiles (strided 4+4 fragments)
//   C[M,N] = A(row-major, lda) @ B(row-major, ldb)   all dims multiples of tile
// EPI 0: C = relu(acc * g_inv[bz])^2            (GEMM1 -> g_S)
// EPI 1: C = acc + bias[row]                    (GEMM2 -> g_T)
// EPI 2: C = acc                                (GEMM3 -> d_out; A=g_S, B=g_T)
// ---------------------------------------------------------------------------
template <int EPI>
__global__ void __launch_bounds__(256, 2)
sgemm128(const float* __restrict__ Ag, int lda, size_t sA,
         const float* __restrict__ Bg, int ldb, size_t sB,
         float* __restrict__ Cg, int ldc, size_t sC,
         int K, const float* __restrict__ bias)
{
    const int bz = blockIdx.z;
    const float* A;
    const float* Bp;
    float* Cp;
    if (EPI == 2) {        // GEMM3: Y = S @ Tview
        A  = g_S + (size_t)bz * sA;
        Bp = g_T + (size_t)bz * sB;
        Cp = Cg  + (size_t)bz * sC;
    } else if (EPI == 0) { // GEMM1: G = M1 @ M2 (both views of x)
        A  = Ag + (size_t)bz * sA;
        Bp = Bg + (size_t)bz * sB;
        Cp = g_S + (size_t)bz * sC;
    } else {               // GEMM2: T = W @ X
        A  = Ag;                       // W, shared across batches
        Bp = Bg + (size_t)bz * sB;
        Cp = g_T + (size_t)bz * sC;
    }

    const int m0 = blockIdx.y * 128;
    const int n0 = blockIdx.x * 128;

    __shared__ float As[8][132];   // padded to reduce transpose-store conflicts
    __shared__ float Bs[8][128];

    const int tid = threadIdx.x;
    const int tx = tid & 15;       // 0..15  -> col groups {tx*4, 64+tx*4}
    const int ty = tid >> 4;       // 0..15  -> row groups {ty*4, 64+ty*4}

    float acc[8][8];
#pragma unroll
    for (int i = 0; i < 8; i++)
#pragma unroll
        for (int j = 0; j < 8; j++) acc[i][j] = 0.f;

    // global-load assignments
    const int arow = tid >> 1;         // 0..127
    const int akq  = (tid & 1) * 4;    // 0 or 4
    const int bk   = tid >> 5;         // 0..7
    const int bn   = (tid & 31) * 4;   // 0..124

    const float* aptr = A  + (size_t)(m0 + arow) * lda + akq;
    const float* bptr = Bp + (size_t)bk * ldb + n0 + bn;

    // prefetch first tiles
    float4 av = *(const float4*)(aptr);
    float4 bv = *(const float4*)(bptr);

    for (int k0 = 0; k0 < K; k0 += 8) {
        __syncthreads();   // previous iteration's reads are done
        As[akq + 0][arow] = av.x;
        As[akq + 1][arow] = av.y;
        As[akq + 2][arow] = av.z;
        As[akq + 3][arow] = av.w;
        *(float4*)&Bs[bk][bn] = bv;
        __syncthreads();

        // prefetch next tiles (overlaps with compute below)
        if (k0 + 8 < K) {
            av = *(const float4*)(aptr + (k0 + 8));
            bv = *(const float4*)(bptr + (size_t)(k0 + 8) * ldb);
        }

#pragma unroll
        for (int k = 0; k < 8; k++) {
            float a[8], b[8];
            *(float4*)&a[0] = *(const float4*)&As[k][ty * 4];
            *(float4*)&a[4] = *(const float4*)&As[k][64 + ty * 4];
            *(float4*)&b[0] = *(const float4*)&Bs[k][tx * 4];
            *(float4*)&b[4] = *(const float4*)&Bs[k][64 + tx * 4];
#pragma unroll
            for (int i = 0; i < 8; i++)
#pragma unroll
                for (int j = 0; j < 8; j++) acc[i][j] = fmaf(a[i], b[j], acc[i][j]);
        }
    }

    // epilogue
    float inv = 0.f;
    if (EPI == 0) inv = g_inv[bz];

#pragma unroll
    for (int ri = 0; ri < 2; ri++) {
#pragma unroll
        for (int i = 0; i < 4; i++) {
            const int gr = m0 + ri * 64 + ty * 4 + i;
            float brow = 0.f;
            if (EPI == 1) brow = bias[gr];
#pragma unroll
            for (int ci = 0; ci < 2; ci++) {
                float4 v;
                v.x = acc[ri * 4 + i][ci * 4 + 0];
                v.y = acc[ri * 4 + i][ci * 4 + 1];
                v.z = acc[ri * 4 + i][ci * 4 + 2];
                v.w = acc[ri * 4 + i][ci * 4 + 3];
                if (EPI == 0) {
                    float r;
                    r = fmaxf(v.x * inv, 0.f); v.x = r * r;
                    r = fmaxf(v.y * inv, 0.f); v.y = r * r;
                    r = fmaxf(v.z * inv, 0.f); v.z = r * r;
                    r = fmaxf(v.w * inv, 0.f); v.w = r * r;
                } else if (EPI == 1) {
                    v.x += brow; v.y += brow; v.z += brow; v.w += brow;
                }
                *(float4*)&Cp[(size_t)gr * ldc + n0 + ci * 64 + tx * 4] = v;
            }
        }
    }
}

// ---------------------------------------------------------------------------
// Launch
//   d_in[0] = x    (16,256,48,48) f32
//   d_in[1] = W    (256,256)      f32
//   d_in[2] = bias (256,)         f32
//   d_out   = y    (16,256,48,48) f32
// ---------------------------------------------------------------------------
extern "C" void kernel_launch(void* const* d_in, const int* in_sizes, int n_in,
                              void* d_out, int out_size)
{
    const float* x    = (const float*)d_in[0];
    const float* W    = (const float*)d_in[1];
    const float* bias = (const float*)d_in[2];
    float* out        = (float*)d_out;

    // 1) per-batch 1/||x||^2
    sumsq_kernel<<<BATCH, 512>>>(x);

    // 2) GEMM2: T[o,p] = W @ X + bias   (independent of step 1)
    {
        dim3 grid(HWDIM / 128, CDIM / 128, BATCH);
        sgemm128<1><<<grid, 256>>>(W, CDIM, 0,
                                   x, HWDIM, (size_t)PB,
                                   nullptr, HWDIM, (size_t)PB,
                                   CDIM, bias);
    }

    // 3) GEMM1: S[n,m] = relu( (M1 @ M2) * inv )^2
    {
        dim3 grid(HWDIM / 128, HWDIM / 128, BATCH);
        sgemm128<0><<<grid, 256>>>(x, CDIM, (size_t)PB,
                                   x, HWDIM, (size_t)PB,
                                   nullptr, HWDIM, (size_t)HWDIM * HWDIM,
                                   CDIM, nullptr);
    }

    // 4) GEMM3: Y[n,j] = S @ Tview  -> d_out directly
    {
        dim3 grid(CDIM / 128, HWDIM / 128, BATCH);
        sgemm128<2><<<grid, 256>>>(nullptr, HWDIM, (size_t)HWDIM * HWDIM,
                                   nullptr, CDIM, (size_t)PB,
                                   out, CDIM, (size_t)PB,
                                   HWDIM, nullptr);
    }
}

// round 4
// speedup vs baseline: 1.0019x; 1.0014x over previous
#include <cuda_runtime.h>

#define BATCH 16
#define CDIM 256
#define HWDIM 2304
#define PB (CDIM * HWDIM)            // 589824 floats per batch

// Scratch (device globals — allocation-free per harness rules)
__device__ float g_inv[BATCH];
__device__ float g_S[(size_t)BATCH * HWDIM * HWDIM];   // 339.7 MB: relu(G*inv)^2
__device__ float g_T[(size_t)BATCH * PB];              // 37.7 MB : 1x1-conv result

// ---------------------------------------------------------------------------
// Kernel 1: per-batch inverse squared L2 norm
// ---------------------------------------------------------------------------
__global__ void sumsq_kernel(const float* __restrict__ x) {
    const int b = blockIdx.x;
    const float4* p = (const float4*)(x + (size_t)b * PB);
    const int n4 = PB / 4;  // 147456
    float s = 0.f;
    for (int i = threadIdx.x; i < n4; i += blockDim.x) {
        float4 v = p[i];
        s += v.x * v.x + v.y * v.y + v.z * v.z + v.w * v.w;
    }
    __shared__ float red[512];
    red[threadIdx.x] = s;
    __syncthreads();
    for (int off = blockDim.x >> 1; off > 0; off >>= 1) {
        if (threadIdx.x < (unsigned)off) red[threadIdx.x] += red[threadIdx.x + off];
        __syncthreads();
    }
    if (threadIdx.x == 0) g_inv[b] = 1.0f / red[0];
}

// ---------------------------------------------------------------------------
// Generic 128x128x8 SGEMM, 256 threads, 8x8 microtiles (strided 4+4 fragments)
//   C[M,N] = A(row-major, lda) @ B(row-major, ldb)   all dims multiples of tile
// EPI 0: C = relu(acc * g_inv[bz])^2            (GEMM1 -> g_S)
// EPI 1: C = acc + bias[row]                    (GEMM2 -> g_T)
// EPI 2: C = acc                                (GEMM3 -> d_out; A=g_S, B=g_T)
// ---------------------------------------------------------------------------
template <int EPI>
__global__ void __launch_bounds__(256, 2)
sgemm128(const float* __restrict__ Ag, int lda, size_t sA,
         const float* __restrict__ Bg, int ldb, size_t sB,
         float* __restrict__ Cg, int ldc, size_t sC,
         int K, const float* __restrict__ bias)
{
    const int bz = blockIdx.z;
    const float* A;
    const float* Bp;
    float* Cp;
    if (EPI == 2) {        // GEMM3: Y = S @ Tview
        A  = g_S + (size_t)bz * sA;
        Bp = g_T + (size_t)bz * sB;
        Cp = Cg  + (size_t)bz * sC;
    } else if (EPI == 0) { // GEMM1: G = M1 @ M2 (both views of x)
        A  = Ag + (size_t)bz * sA;
        Bp = Bg + (size_t)bz * sB;
        Cp = g_S + (size_t)bz * sC;
    } else {               // GEMM2: T = W @ X
        A  = Ag;                       // W, shared across batches
        Bp = Bg + (size_t)bz * sB;
        Cp = g_T + (size_t)bz * sC;
    }

    const int m0 = blockIdx.y * 128;
    const int n0 = blockIdx.x * 128;

    __shared__ float As[8][132];   // padded to reduce transpose-store conflicts
    __shared__ float Bs[8][128];

    const int tid = threadIdx.x;
    const int tx = tid & 15;       // 0..15  -> col groups {tx*4, 64+tx*4}
    const int ty = tid >> 4;       // 0..15  -> row groups {ty*4, 64+ty*4}

    float acc[8][8];
#pragma unroll
    for (int i = 0; i < 8; i++)
#pragma unroll
        for (int j = 0; j < 8; j++) acc[i][j] = 0.f;

    // global-load assignments
    const int arow = tid >> 1;         // 0..127
    const int akq  = (tid & 1) * 4;    // 0 or 4
    const int bk   = tid >> 5;         // 0..7
    const int bn   = (tid & 31) * 4;   // 0..124

    const float* aptr = A  + (size_t)(m0 + arow) * lda + akq;
    const float* bptr = Bp + (size_t)bk * ldb + n0 + bn;

    // prefetch first tiles
    float4 av = *(const float4*)(aptr);
    float4 bv = *(const float4*)(bptr);

    for (int k0 = 0; k0 < K; k0 += 8) {
        __syncthreads();   // previous iteration's reads are done
        As[akq + 0][arow] = av.x;
        As[akq + 1][arow] = av.y;
        As[akq + 2][arow] = av.z;
        As[akq + 3][arow] = av.w;
        *(float4*)&Bs[bk][bn] = bv;
        __syncthreads();

        // prefetch next tiles (overlaps with compute below)
        if (k0 + 8 < K) {
            av = *(const float4*)(aptr + (k0 + 8));
            bv = *(const float4*)(bptr + (size_t)(k0 + 8) * ldb);
        }

#pragma unroll
        for (int k = 0; k < 8; k++) {
            float a[8], b[8];
            *(float4*)&a[0] = *(const float4*)&As[k][ty * 4];
            *(float4*)&a[4] = *(const float4*)&As[k][64 + ty * 4];
            *(float4*)&b[0] = *(const float4*)&Bs[k][tx * 4];
            *(float4*)&b[4] = *(const float4*)&Bs[k][64 + tx * 4];
#pragma unroll
            for (int i = 0; i < 8; i++)
#pragma unroll
                for (int j = 0; j < 8; j++) acc[i][j] = fmaf(a[i], b[j], acc[i][j]);
        }
    }

    // epilogue
    float inv = 0.f;
    if (EPI == 0) inv = g_inv[bz];

#pragma unroll
    for (int ri = 0; ri < 2; ri++) {
#pragma unroll
        for (int i = 0; i < 4; i++) {
            const int gr = m0 + ri * 64 + ty * 4 + i;
            float brow = 0.f;
            if (EPI == 1) brow = bias[gr];
#pragma unroll
            for (int ci = 0; ci < 2; ci++) {
                float4 v;
                v.x = acc[ri * 4 + i][ci * 4 + 0];
                v.y = acc[ri * 4 + i][ci * 4 + 1];
                v.z = acc[ri * 4 + i][ci * 4 + 2];
                v.w = acc[ri * 4 + i][ci * 4 + 3];
                if (EPI == 0) {
                    float r;
                    r = fmaxf(v.x * inv, 0.f); v.x = r * r;
                    r = fmaxf(v.y * inv, 0.f); v.y = r * r;
                    r = fmaxf(v.z * inv, 0.f); v.z = r * r;
                    r = fmaxf(v.w * inv, 0.f); v.w = r * r;
                } else if (EPI == 1) {
                    v.x += brow; v.y += brow; v.z += brow; v.w += brow;
                }
                *(float4*)&Cp[(size_t)gr * ldc + n0 + ci * 64 + tx * 4] = v;
            }
        }
    }
}

// ---------------------------------------------------------------------------
// Launch
//   d_in[0] = x    (16,256,48,48) f32
//   d_in[1] = W    (256,256)      f32
//   d_in[2] = bias (256,)         f32
//   d_out   = y    (16,256,48,48) f32
// ---------------------------------------------------------------------------
extern "C" void kernel_launch(void* const* d_in, const int* in_sizes, int n_in,
                              void* d_out, int out_size)
{
    const float* x    = (const float*)d_in[0];
    const float* W    = (const float*)d_in[1];
    const float* bias = (const float*)d_in[2];
    float* out        = (float*)d_out;

    // 1) per-batch 1/||x||^2
    sumsq_kernel<<<BATCH, 512>>>(x);

    // 2) GEMM2: T[o,p] = W @ X + bias   (independent of step 1)
    {
        dim3 grid(HWDIM / 128, CDIM / 128, BATCH);
        sgemm128<1><<<grid, 256>>>(W, CDIM, 0,
                                   x, HWDIM, (size_t)PB,
                                   nullptr, HWDIM, (size_t)PB,
                                   CDIM, bias);
    }

    // 3) GEMM1: S[n,m] = relu( (M1 @ M2) * inv )^2
    {
        dim3 grid(HWDIM / 128, HWDIM / 128, BATCH);
        sgemm128<0><<<grid, 256>>>(x, CDIM, (size_t)PB,
                                   x, HWDIM, (size_t)PB,
                                   nullptr, HWDIM, (size_t)HWDIM * HWDIM,
                                   CDIM, nullptr);
    }

    // 4) GEMM3: Y[n,j] = S @ Tview  -> d_out directly
    {
        dim3 grid(CDIM / 128, HWDIM / 128, BATCH);
        sgemm128<2><<<grid, 256>>>(nullptr, HWDIM, (size_t)HWDIM * HWDIM,
                                   nullptr, CDIM, (size_t)PB,
                                   out, CDIM, (size_t)PB,
                                   HWDIM, nullptr);
    }
}

// round 6
// speedup vs baseline: 1.6080x; 1.6051x over previous
#include <cuda_runtime.h>
#include <cuda_bf16.h>
#include <cstdint>

#define BATCH 16
#define CDIM 256
#define HWDIM 2304
#define PB (CDIM * HWDIM)

#define NST 3
#define STG_B 40960                 // (Ahi+Alo+Bhi+Blo) * 128 rows * 80B
#define SMEM_B (NST * STG_B)        // 122880

// ---------------------------------------------------------------------------
// Device scratch (allocation-free)
// ---------------------------------------------------------------------------
__device__ float g_inv[BATCH];
__device__ float g_T[(size_t)BATCH * PB];
__device__ __align__(1024) __nv_bfloat16 g_Xhi[(size_t)BATCH * PB];
__device__ __align__(1024) __nv_bfloat16 g_Xlo[(size_t)BATCH * PB];
__device__ __align__(1024) __nv_bfloat16 g_XThi[(size_t)BATCH * PB];
__device__ __align__(1024) __nv_bfloat16 g_XTlo[(size_t)BATCH * PB];
__device__ __align__(1024) __nv_bfloat16 g_Whi[CDIM * CDIM];
__device__ __align__(1024) __nv_bfloat16 g_Wlo[CDIM * CDIM];
__device__ __align__(1024) __nv_bfloat16 g_Shi[(size_t)BATCH * HWDIM * HWDIM];
__device__ __align__(1024) __nv_bfloat16 g_Slo[(size_t)BATCH * HWDIM * HWDIM];
__device__ __align__(1024) __nv_bfloat16 g_TThi[(size_t)BATCH * PB];
__device__ __align__(1024) __nv_bfloat16 g_TTlo[(size_t)BATCH * PB];

// ---------------------------------------------------------------------------
// per-batch 1/||x||^2
// ---------------------------------------------------------------------------
__global__ void sumsq_kernel(const float* __restrict__ x) {
    const int b = blockIdx.x;
    const float4* p = (const float4*)(x + (size_t)b * PB);
    float s = 0.f;
    for (int i = threadIdx.x; i < PB / 4; i += blockDim.x) {
        float4 v = p[i];
        s += v.x * v.x + v.y * v.y + v.z * v.z + v.w * v.w;
    }
    __shared__ float red[512];
    red[threadIdx.x] = s;
    __syncthreads();
    for (int off = blockDim.x >> 1; off > 0; off >>= 1) {
        if (threadIdx.x < (unsigned)off) red[threadIdx.x] += red[threadIdx.x + off];
        __syncthreads();
    }
    if (threadIdx.x == 0) g_inv[b] = 1.0f / red[0];
}

// ---------------------------------------------------------------------------
// f32 -> bf16 hi/lo split (flat)
// ---------------------------------------------------------------------------
__device__ __forceinline__ uint32_t packbf(float a, float b) {
    __nv_bfloat16 ha = __float2bfloat16(a), hb = __float2bfloat16(b);
    return (uint32_t)__bfloat16_as_ushort(ha) | ((uint32_t)__bfloat16_as_ushort(hb) << 16);
}
__global__ void split_flat(const float4* __restrict__ in,
                           uint2* __restrict__ hi, uint2* __restrict__ lo, int n4) {
    int i = blockIdx.x * blockDim.x + threadIdx.x;
    if (i >= n4) return;
    float4 v = in[i];
    __nv_bfloat16 h0 = __float2bfloat16(v.x), h1 = __float2bfloat16(v.y);
    __nv_bfloat16 h2 = __float2bfloat16(v.z), h3 = __float2bfloat16(v.w);
    uint2 hp, lp;
    hp.x = (uint32_t)__bfloat16_as_ushort(h0) | ((uint32_t)__bfloat16_as_ushort(h1) << 16);
    hp.y = (uint32_t)__bfloat16_as_ushort(h2) | ((uint32_t)__bfloat16_as_ushort(h3) << 16);
    lp.x = packbf(v.x - __bfloat162float(h0), v.y - __bfloat162float(h1));
    lp.y = packbf(v.z - __bfloat162float(h2), v.w - __bfloat162float(h3));
    hi[i] = hp;
    lo[i] = lp;
}

// ---------------------------------------------------------------------------
// per-batch transpose + split: in [rows,cols] f32 -> out [cols,rows] bf16 hi/lo
// ---------------------------------------------------------------------------
__global__ void transpose_split(const float* __restrict__ in,
                                __nv_bfloat16* __restrict__ hi,
                                __nv_bfloat16* __restrict__ lo,
                                int rows, int cols) {
    __shared__ float t[32][33];
    const size_t off = (size_t)blockIdx.z * rows * cols;
    const int c0 = blockIdx.x * 32, r0 = blockIdx.y * 32;
    const int x = threadIdx.x, y0 = threadIdx.y;
#pragma unroll
    for (int yy = y0; yy < 32; yy += 8)
        t[yy][x] = in[off + (size_t)(r0 + yy) * cols + c0 + x];
    __syncthreads();
#pragma unroll
    for (int yy = y0; yy < 32; yy += 8) {
        float v = t[x][yy];
        __nv_bfloat16 h = __float2bfloat16(v);
        size_t o = off + (size_t)(c0 + yy) * rows + r0 + x;
        hi[o] = h;
        lo[o] = __float2bfloat16(v - __bfloat162float(h));
    }
}

// ---------------------------------------------------------------------------
// PTX helpers (sm_80 baseline — compile on plain compute_103)
// ---------------------------------------------------------------------------
__device__ __forceinline__ uint32_t s2u(const void* p) {
    uint32_t a;
    asm("{ .reg .u64 t; cvta.to.shared.u64 t, %1; cvt.u32.u64 %0, t; }" : "=r"(a) : "l"(p));
    return a;
}
__device__ __forceinline__ void cp16(uint32_t d, const void* g) {
    asm volatile("cp.async.cg.shared.global [%0], [%1], 16;" :: "r"(d), "l"(g));
}
#define LDM4(r, addr) \
    asm volatile("ldmatrix.sync.aligned.m8n8.x4.shared.b16 {%0,%1,%2,%3}, [%4];" \
        : "=r"((r)[0]), "=r"((r)[1]), "=r"((r)[2]), "=r"((r)[3]) : "r"(addr))
#define LDM2(r, addr) \
    asm volatile("ldmatrix.sync.aligned.m8n8.x2.shared.b16 {%0,%1}, [%2];" \
        : "=r"((r)[0]), "=r"((r)[1]) : "r"(addr))
#define MMA16816(c, a, b) \
    asm volatile("mma.sync.aligned.m16n8k16.row.col.f32.bf16.bf16.f32 " \
        "{%0,%1,%2,%3}, {%4,%5,%6,%7}, {%8,%9}, {%0,%1,%2,%3};" \
        : "+f"((c)[0]), "+f"((c)[1]), "+f"((c)[2]), "+f"((c)[3]) \
        : "r"((a)[0]), "r"((a)[1]), "r"((a)[2]), "r"((a)[3]), "r"((b)[0]), "r"((b)[1]))

// ---------------------------------------------------------------------------
// bf16 mma.sync GEMM, CTA 128x128, KC=32, 3-term fp32 emulation
//   D[m,n] = sum_k A[m,k]*B[n,k]   (A:[M,K], B:[N,K], both K-major bf16 hi/lo)
// EPI 0: S = relu(acc*g_inv[bz])^2 -> g_Shi/g_Slo (bf16 hi/lo)
// EPI 1: T = acc + bias[row]        -> g_T (f32, ld 2304)
// EPI 2: Y = acc                    -> outY (f32, ld 256)
// ---------------------------------------------------------------------------
template <int EPI>
__global__ void __launch_bounds__(256, 1)
mm_bf16(const __nv_bfloat16* __restrict__ Ah, const __nv_bfloat16* __restrict__ Al,
        const __nv_bfloat16* __restrict__ Bh, const __nv_bfloat16* __restrict__ Bl,
        int lda, int ldb, size_t bA, size_t bB, int K,
        const float* __restrict__ bias, float* __restrict__ outY)
{
    extern __shared__ char smv[];
    const uint32_t sb = s2u(smv);
    const int tid = threadIdx.x;
    const int bz = blockIdx.z;
    const int m0 = blockIdx.y * 128, n0 = blockIdx.x * 128;
    const int w = tid >> 5, l = tid & 31;
    const int wm = w >> 2, wn = w & 3;

    // loader constants: thread handles rows lr and lr+64, 16B chunk lq, all 4 buffers
    const int lr = tid >> 2, lq = tid & 3;
    const __nv_bfloat16* pAh = Ah + (size_t)bz * bA + (size_t)(m0 + lr) * lda + lq * 8;
    const __nv_bfloat16* pAl = Al + (size_t)bz * bA + (size_t)(m0 + lr) * lda + lq * 8;
    const __nv_bfloat16* pBh = Bh + (size_t)bz * bB + (size_t)(n0 + lr) * ldb + lq * 8;
    const __nv_bfloat16* pBl = Bl + (size_t)bz * bB + (size_t)(n0 + lr) * ldb + lq * 8;
    const uint32_t dBase = sb + lr * 80 + lq * 16;
    const int sA64 = 64 * lda, sB64 = 64 * ldb;

    // fragment lane constants
    const int sub = l >> 3;
    const uint32_t aOff = (uint32_t)((wm * 64 + (sub & 1) * 8 + (l & 7)) * 80 + ((sub >> 1) * 8) * 2);
    const uint32_t bOff = (uint32_t)(20480 + (wn * 32 + (l & 7)) * 80 + (((l >> 3) & 1) * 8) * 2);

    float acc[4][4][4];
#pragma unroll
    for (int i = 0; i < 4; i++)
#pragma unroll
        for (int j = 0; j < 4; j++)
#pragma unroll
            for (int q = 0; q < 4; q++) acc[i][j][q] = 0.f;

#define LOAD_STAGE(kc, slot) do { \
        uint32_t d = dBase + (slot) * STG_B; \
        int ko = (kc) * 32; \
        cp16(d,         pAh + ko); \
        cp16(d + 5120,  pAh + ko + sA64); \
        cp16(d + 10240, pAl + ko); \
        cp16(d + 15360, pAl + ko + sA64); \
        cp16(d + 20480, pBh + ko); \
        cp16(d + 25600, pBh + ko + sB64); \
        cp16(d + 30720, pBl + ko); \
        cp16(d + 35840, pBl + ko + sB64); \
        asm volatile("cp.async.commit_group;"); \
    } while (0)

    const int KN = K / 32;
    LOAD_STAGE(0, 0);
    LOAD_STAGE(1, 1);

    int slot = 0;
    for (int kc = 0; kc < KN; kc++) {
        asm volatile("cp.async.wait_group 1;");
        __syncthreads();
        if (kc + 2 < KN) LOAD_STAGE(kc + 2, (kc + 2) % NST);
        const uint32_t s0 = sb + slot * STG_B;
        slot++; if (slot == NST) slot = 0;
#pragma unroll
        for (int ks = 0; ks < 2; ks++) {
            const uint32_t a0 = s0 + aOff + ks * 32;
            const uint32_t b0 = s0 + bOff + ks * 32;
            uint32_t afh[4][4], afl[4][4], bfh[4][2], bfl[4][2];
#pragma unroll
            for (int i = 0; i < 4; i++) {
                LDM4(afh[i], a0 + i * 1280);
                LDM4(afl[i], a0 + i * 1280 + 10240);
            }
#pragma unroll
            for (int j = 0; j < 4; j++) {
                LDM2(bfh[j], b0 + j * 640);
                LDM2(bfl[j], b0 + j * 640 + 10240);
            }
#pragma unroll
            for (int i = 0; i < 4; i++)
#pragma unroll
                for (int j = 0; j < 4; j++) {
                    MMA16816(acc[i][j], afh[i], bfh[j]);
                    MMA16816(acc[i][j], afh[i], bfl[j]);
                    MMA16816(acc[i][j], afl[i], bfh[j]);
                }
        }
    }

    // epilogue
    float inv = 0.f;
    if (EPI == 0) inv = g_inv[bz];
    const int quad = l >> 2, tq = l & 3;
#pragma unroll
    for (int i = 0; i < 4; i++) {
#pragma unroll
        for (int half = 0; half < 2; half++) {
            const int r = m0 + wm * 64 + i * 16 + quad + half * 8;
            float bvv = 0.f;
            if (EPI == 1) bvv = bias[r];
#pragma unroll
            for (int j = 0; j < 4; j++) {
                const int col = n0 + wn * 32 + j * 8 + tq * 2;
                float v0 = acc[i][j][half * 2 + 0];
                float v1 = acc[i][j][half * 2 + 1];
                if (EPI == 0) {
                    v0 = fmaxf(v0 * inv, 0.f); v0 *= v0;
                    v1 = fmaxf(v1 * inv, 0.f); v1 *= v1;
                    __nv_bfloat16 h0 = __float2bfloat16(v0), h1 = __float2bfloat16(v1);
                    uint32_t hp = (uint32_t)__bfloat16_as_ushort(h0) | ((uint32_t)__bfloat16_as_ushort(h1) << 16);
                    uint32_t lp = packbf(v0 - __bfloat162float(h0), v1 - __bfloat162float(h1));
                    size_t base = (size_t)bz * HWDIM * HWDIM + (size_t)r * HWDIM + col;
                    *(uint32_t*)(g_Shi + base) = hp;
                    *(uint32_t*)(g_Slo + base) = lp;
                } else if (EPI == 1) {
                    float2 vv; vv.x = v0 + bvv; vv.y = v1 + bvv;
                    *(float2*)(g_T + (size_t)bz * PB + (size_t)r * HWDIM + col) = vv;
                } else {
                    float2 vv; vv.x = v0; vv.y = v1;
                    *(float2*)(outY + (size_t)bz * PB + (size_t)r * CDIM + col) = vv;
                }
            }
        }
    }
#undef LOAD_STAGE
}

// ---------------------------------------------------------------------------
// Host launch
// ---------------------------------------------------------------------------
extern "C" void kernel_launch(void* const* d_in, const int* in_sizes, int n_in,
                              void* d_out, int out_size)
{
    const float* x    = (const float*)d_in[0];
    const float* W    = (const float*)d_in[1];
    const float* bias = (const float*)d_in[2];
    float* out        = (float*)d_out;

    void *pXhi, *pXlo, *pXThi, *pXTlo, *pWhi, *pWlo, *pShi, *pSlo, *pTThi, *pTTlo, *pT;
    cudaGetSymbolAddress(&pXhi,  g_Xhi);
    cudaGetSymbolAddress(&pXlo,  g_Xlo);
    cudaGetSymbolAddress(&pXThi, g_XThi);
    cudaGetSymbolAddress(&pXTlo, g_XTlo);
    cudaGetSymbolAddress(&pWhi,  g_Whi);
    cudaGetSymbolAddress(&pWlo,  g_Wlo);
    cudaGetSymbolAddress(&pShi,  g_Shi);
    cudaGetSymbolAddress(&pSlo,  g_Slo);
    cudaGetSymbolAddress(&pTThi, g_TThi);
    cudaGetSymbolAddress(&pTTlo, g_TTlo);
    cudaGetSymbolAddress(&pT,    g_T);

    static bool attr_done = false;
    if (!attr_done) {
        cudaFuncSetAttribute(mm_bf16<0>, cudaFuncAttributeMaxDynamicSharedMemorySize, SMEM_B);
        cudaFuncSetAttribute(mm_bf16<1>, cudaFuncAttributeMaxDynamicSharedMemorySize, SMEM_B);
        cudaFuncSetAttribute(mm_bf16<2>, cudaFuncAttributeMaxDynamicSharedMemorySize, SMEM_B);
        attr_done = true;
    }

    // 1) norm
    sumsq_kernel<<<BATCH, 512>>>(x);

    // 2) splits
    split_flat<<<(BATCH * PB / 4 + 255) / 256, 256>>>((const float4*)x, (uint2*)pXhi, (uint2*)pXlo, BATCH * PB / 4);
    split_flat<<<(CDIM * CDIM / 4 + 255) / 256, 256>>>((const float4*)W, (uint2*)pWhi, (uint2*)pWlo, CDIM * CDIM / 4);
    {   // XT = transpose(x viewed [256,2304]) -> [2304,256]
        dim3 g(HWDIM / 32, CDIM / 32, BATCH);
        transpose_split<<<g, dim3(32, 8)>>>(x, (__nv_bfloat16*)pXThi, (__nv_bfloat16*)pXTlo, CDIM, HWDIM);
    }

    // 3) GEMM2: T[o,p] = W @ x2 + bias      (M=256, N=2304, K=256)
    mm_bf16<1><<<dim3(HWDIM / 128, CDIM / 128, BATCH), 256, SMEM_B>>>(
        (const __nv_bfloat16*)pWhi, (const __nv_bfloat16*)pWlo,
        (const __nv_bfloat16*)pXThi, (const __nv_bfloat16*)pXTlo,
        CDIM, CDIM, 0, (size_t)PB, CDIM, bias, nullptr);

    // 4) TT = transpose(T viewed [2304,256]) -> [256,2304]
    {
        dim3 g(CDIM / 32, HWDIM / 32, BATCH);
        transpose_split<<<g, dim3(32, 8)>>>((const float*)pT,
            (__nv_bfloat16*)pTThi, (__nv_bfloat16*)pTTlo, HWDIM, CDIM);
    }

    // 5) GEMM1: S = relu((x1 @ x2) * inv)^2   (M=N=2304, K=256)
    mm_bf16<0><<<dim3(HWDIM / 128, HWDIM / 128, BATCH), 256, SMEM_B>>>(
        (const __nv_bfloat16*)pXhi, (const __nv_bfloat16*)pXlo,
        (const __nv_bfloat16*)pXThi, (const __nv_bfloat16*)pXTlo,
        CDIM, CDIM, (size_t)PB, (size_t)PB, CDIM, nullptr, nullptr);

    // 6) GEMM3: Y = S @ Tview -> out          (M=2304, N=256, K=2304)
    mm_bf16<2><<<dim3(CDIM / 128, HWDIM / 128, BATCH), 256, SMEM_B>>>(
        (const __nv_bfloat16*)pShi, (const __nv_bfloat16*)pSlo,
        (const __nv_bfloat16*)pTThi, (const __nv_bfloat16*)pTTlo,
        HWDIM, HWDIM, (size_t)HWDIM * HWDIM, (size_t)PB, HWDIM, nullptr, out);
}